// round 11
// baseline (speedup 1.0000x reference)
#include <cuda_runtime.h>
#include <cuda_fp16.h>
#include <cstdint>
#include <cstddef>
#include <math.h>

#define BB   4
#define SS   4096
#define TT   512
#define DM   1024
#define DT   768
#define NH   16
#define NKVH 2
#define HD   64
#define REPH 8
#define KVW  256

// ---------------- scratch (all half) ------------------------------------------
__device__ __half g_xh [(size_t)BB * SS * DM];
__device__ __half g_tn [(size_t)BB * TT * DT];
__device__ __half g_kv [(size_t)BB * TT * KVW];
__device__ __half g_q  [(size_t)BB * SS * DM];
__device__ __half g_o  [(size_t)BB * SS * DM];
__device__ __half g_wqt  [(size_t)DM * DM];
__device__ __half g_wkvt [(size_t)KVW * DT];
__device__ __half g_woutt[(size_t)DM * DM];

// ---------------- PTX helpers ---------------------------------------------------
__device__ __forceinline__ uint32_t smem_u32(const void* p) {
    uint32_t a;
    asm("{ .reg .u64 t; cvta.to.shared.u64 t, %1; cvt.u32.u64 %0, t; }" : "=r"(a) : "l"(p));
    return a;
}
__device__ __forceinline__ void cp16(uint32_t s, const void* g) {
    asm volatile("cp.async.cg.shared.global [%0], [%1], 16;" :: "r"(s), "l"(g));
}
__device__ __forceinline__ void cp_commit() { asm volatile("cp.async.commit_group;"); }
template<int N> __device__ __forceinline__ void cp_wait() {
    asm volatile("cp.async.wait_group %0;" :: "n"(N) : "memory");
}
__device__ __forceinline__ uint32_t h2pack(float lo, float hi) {
    uint32_t r;
    asm("cvt.rn.f16x2.f32 %0, %1, %2;" : "=r"(r) : "f"(hi), "f"(lo));
    return r;
}
__device__ __forceinline__ void mma_f16(float* c, const uint32_t* a, const uint32_t* b) {
    asm volatile(
        "mma.sync.aligned.m16n8k16.row.col.f32.f16.f16.f32 "
        "{%0,%1,%2,%3}, {%4,%5,%6,%7}, {%8,%9}, {%0,%1,%2,%3};"
        : "+f"(c[0]), "+f"(c[1]), "+f"(c[2]), "+f"(c[3])
        : "r"(a[0]), "r"(a[1]), "r"(a[2]), "r"(a[3]), "r"(b[0]), "r"(b[1]));
}
__device__ __forceinline__ void ldsm4(uint32_t& r0, uint32_t& r1, uint32_t& r2, uint32_t& r3,
                                      uint32_t a) {
    asm volatile("ldmatrix.sync.aligned.m8n8.x4.shared.b16 {%0,%1,%2,%3}, [%4];"
                 : "=r"(r0), "=r"(r1), "=r"(r2), "=r"(r3) : "r"(a));
}
__device__ __forceinline__ void ldsm4t(uint32_t& r0, uint32_t& r1, uint32_t& r2, uint32_t& r3,
                                       uint32_t a) {
    asm volatile("ldmatrix.sync.aligned.m8n8.x4.trans.shared.b16 {%0,%1,%2,%3}, [%4];"
                 : "=r"(r0), "=r"(r1), "=r"(r2), "=r"(r3) : "r"(a));
}

#define GSTR 72                         // smem row stride (halfs), 64-k slabs
#define STGB (256 * GSTR * 2)           // bytes per stage (A 128 rows + B 128 rows)
#define QSCALE 0.1803368801111204f      // 0.125 * log2(e)

// ---------------- shared GEMM slab primitives ---------------------------------------
__device__ __forceinline__ void load_slab_ptr(const __half* __restrict__ A, int lda,
                                              const __half* __restrict__ B, int ldb,
                                              int row0, int col0, int k0,
                                              uint32_t base, int tid) {
#pragma unroll
    for (int t = 0; t < 4; t++) {
        const int idx = tid + t * 256;
        const int r = idx >> 3, c = (idx & 7) * 8;
        cp16(base + (uint32_t)(r * GSTR + c) * 2u,
             A + (size_t)(row0 + r) * lda + k0 + c);
    }
#pragma unroll
    for (int t = 0; t < 4; t++) {
        const int idx = tid + t * 256;
        const int r = idx >> 3, c = (idx & 7) * 8;
        cp16(base + (uint32_t)((128 + r) * GSTR + c) * 2u,
             B + (size_t)(col0 + r) * ldb + k0 + c);
    }
}

__device__ __forceinline__ void compute_slab(float acc[4][4][4], uint32_t sbase,
                                             uint32_t aoff, uint32_t boff) {
#pragma unroll
    for (int ks = 0; ks < 4; ks++) {
        const uint32_t kb = (uint32_t)(ks * 32);
        uint32_t af[4][4], bf[4][2];
#pragma unroll
        for (int m = 0; m < 4; m++)
            ldsm4(af[m][0], af[m][1], af[m][2], af[m][3],
                  sbase + aoff + (uint32_t)(m * 16 * GSTR * 2) + kb);
#pragma unroll
        for (int nb = 0; nb < 2; nb++) {
            uint32_t q0, q1, q2, q3;
            ldsm4(q0, q1, q2, q3,
                  sbase + boff + (uint32_t)(nb * 16 * GSTR * 2) + kb);
            bf[2 * nb][0] = q0; bf[2 * nb][1] = q2;
            bf[2 * nb + 1][0] = q1; bf[2 * nb + 1][1] = q3;
        }
#pragma unroll
        for (int m = 0; m < 4; m++)
#pragma unroll
            for (int n = 0; n < 4; n++)
                mma_f16(acc[m][n], af[m], bf[n]);
    }
}

// ---------------- persistent Q+KV projection kernel ----------------------------------
// tiles 0..1023: Q (16 slabs each); tiles 1024..1055: KV (12 slabs each)
__global__ void __launch_bounds__(256, 2)
qkv_gemm_k() {
    extern __shared__ __half hsm[];
    const uint32_t smb = smem_u32(hsm);
    const int tid  = threadIdx.x;
    const int wid  = tid >> 5;
    const int lane = tid & 31;
    const int R0   = (wid >> 2) * 64;
    const int C0   = (wid & 3) * 32;
    const int g    = lane >> 2;
    const int qd   = lane & 3;
    const int l15  = lane & 15;
    const int kh   = (lane >> 4) << 3;
    const uint32_t aoff = (uint32_t)((R0 + l15) * GSTR + kh) * 2u;
    const uint32_t boff = (uint32_t)((128 + C0 + l15) * GSTR + kh) * 2u;

    const int G = gridDim.x;
    const int bid = blockIdx.x;
    const int NT = 1056;

    int total = 0;
    for (int t = bid; t < NT; t += G) total += (t < 1024) ? 16 : 12;
    if (total == 0) return;

    int lt = bid, lslab = 0;
    auto loadcur = [&](uint32_t buf) {
        if (lt < 1024) {
            load_slab_ptr(g_xh, DM, g_wqt, DM,
                          (lt >> 3) * 128, (lt & 7) * 128, lslab * 64,
                          smb + buf * (uint32_t)STGB, tid);
            if (++lslab == 16) { lslab = 0; lt += G; }
        } else {
            const int k = lt - 1024;
            load_slab_ptr(g_tn, DT, g_wkvt, DT,
                          (k >> 1) * 128, (k & 1) * 128, lslab * 64,
                          smb + buf * (uint32_t)STGB, tid);
            if (++lslab == 12) { lslab = 0; lt += G; }
        }
    };

    const int npro = (total < 2) ? total : 2;
    for (int p = 0; p < npro; p++) { loadcur((uint32_t)p); cp_commit(); }

    int gi = 0;
    for (int tc = bid; tc < NT; tc += G) {
        const int ns = (tc < 1024) ? 16 : 12;
        float acc[4][4][4];
#pragma unroll
        for (int m = 0; m < 4; m++)
#pragma unroll
            for (int n = 0; n < 4; n++)
#pragma unroll
                for (int j = 0; j < 4; j++) acc[m][n][j] = 0.f;

        for (int s = 0; s < ns; s++, gi++) {
            if (gi + 1 < total) cp_wait<1>(); else cp_wait<0>();
            __syncthreads();
            if (gi + 2 < total) { loadcur((uint32_t)((gi + 2) % 3)); cp_commit(); }
            compute_slab(acc, smb + (uint32_t)((gi % 3) * STGB), aoff, boff);
        }

        // epilogue (half output)
        __half* C;
        int ldc, row0, col0;
        float scale;
        if (tc < 1024) {
            C = g_q; ldc = DM; row0 = (tc >> 3) * 128; col0 = (tc & 7) * 128; scale = QSCALE;
        } else {
            const int k = tc - 1024;
            C = g_kv; ldc = KVW; row0 = (k >> 1) * 128; col0 = (k & 1) * 128; scale = 1.f;
        }
#pragma unroll
        for (int m = 0; m < 4; m++)
#pragma unroll
            for (int n = 0; n < 4; n++) {
                const int cc = col0 + C0 + n * 8 + qd * 2;
                const int r0 = row0 + R0 + m * 16 + g;
                *(uint32_t*)(C + (size_t)r0 * ldc + cc) =
                    h2pack(acc[m][n][0] * scale, acc[m][n][1] * scale);
                *(uint32_t*)(C + (size_t)(r0 + 8) * ldc + cc) =
                    h2pack(acc[m][n][2] * scale, acc[m][n][3] * scale);
            }
    }
}

// ---------------- persistent output projection kernel --------------------------------
__global__ void __launch_bounds__(256, 2)
out_gemm_k(const float* __restrict__ bout, float* __restrict__ out) {
    extern __shared__ __half hsm[];
    const uint32_t smb = smem_u32(hsm);
    const int tid  = threadIdx.x;
    const int wid  = tid >> 5;
    const int lane = tid & 31;
    const int R0   = (wid >> 2) * 64;
    const int C0   = (wid & 3) * 32;
    const int g    = lane >> 2;
    const int qd   = lane & 3;
    const int l15  = lane & 15;
    const int kh   = (lane >> 4) << 3;
    const uint32_t aoff = (uint32_t)((R0 + l15) * GSTR + kh) * 2u;
    const uint32_t boff = (uint32_t)((128 + C0 + l15) * GSTR + kh) * 2u;

    const int G = gridDim.x;
    const int bid = blockIdx.x;
    const int NT = 1024;

    int ntloc = 0;
    for (int t = bid; t < NT; t += G) ntloc++;
    const int total = ntloc * 16;
    if (total == 0) return;

    int lt = bid, lslab = 0;
    auto loadcur = [&](uint32_t buf) {
        load_slab_ptr(g_o, DM, g_woutt, DM,
                      (lt >> 3) * 128, (lt & 7) * 128, lslab * 64,
                      smb + buf * (uint32_t)STGB, tid);
        if (++lslab == 16) { lslab = 0; lt += G; }
    };

    const int npro = (total < 2) ? total : 2;
    for (int p = 0; p < npro; p++) { loadcur((uint32_t)p); cp_commit(); }

    int gi = 0;
    for (int tc = bid; tc < NT; tc += G) {
        float acc[4][4][4];
#pragma unroll
        for (int m = 0; m < 4; m++)
#pragma unroll
            for (int n = 0; n < 4; n++)
#pragma unroll
                for (int j = 0; j < 4; j++) acc[m][n][j] = 0.f;

        for (int s = 0; s < 16; s++, gi++) {
            if (gi + 1 < total) cp_wait<1>(); else cp_wait<0>();
            __syncthreads();
            if (gi + 2 < total) { loadcur((uint32_t)((gi + 2) % 3)); cp_commit(); }
            compute_slab(acc, smb + (uint32_t)((gi % 3) * STGB), aoff, boff);
        }

        const int row0 = (tc >> 3) * 128, col0 = (tc & 7) * 128;
#pragma unroll
        for (int m = 0; m < 4; m++)
#pragma unroll
            for (int n = 0; n < 4; n++) {
                const int cc = col0 + C0 + n * 8 + qd * 2;
                const int r0 = row0 + R0 + m * 16 + g;
                const float b0 = __ldg(bout + cc), b1 = __ldg(bout + cc + 1);
                *(float2*)(out + (size_t)r0 * DM + cc) =
                    make_float2(acc[m][n][0] + b0, acc[m][n][1] + b1);
                *(float2*)(out + (size_t)(r0 + 8) * DM + cc) =
                    make_float2(acc[m][n][2] + b0, acc[m][n][3] + b1);
            }
    }
}

// ---------------- fused flash attention (R9 fp32-acc, known-good) --------------------
#define QSTR 72
#define KBUF 4608
#define KOFFH 9216
#define VOFFH (9216 + 2 * KBUF)
__global__ void __launch_bounds__(256, 2)
flash_k() {
    extern __shared__ __half hsm[];
    const int sblk = blockIdx.x;
    const int b = blockIdx.y / NH, h = blockIdx.y % NH, gg = h / REPH;
    const int tid = threadIdx.x, wid = tid >> 5, lane = tid & 31;
    const int g = lane >> 2, qd = lane & 3;
    const int l15 = lane & 15;
    const int kh  = (lane >> 4) << 3;
    const uint32_t smb = smem_u32(hsm);

    const __half* Qg = g_q + ((size_t)b * SS + sblk * 128) * DM + h * HD;
    const __half* Kg = g_kv + (size_t)b * TT * KVW + gg * HD;
    const __half* Vg = g_kv + (size_t)b * TT * KVW + NKVH * HD + gg * HD;

    auto ldkv = [&](int chunk, int buf) {
        const int t0 = chunk * 64;
#pragma unroll
        for (int i = 0; i < 2; i++) {
            const int idx = tid + i * 256;
            const int r = idx >> 3, c = (idx & 7) * 8;
            cp16(smb + (uint32_t)(KOFFH + buf * KBUF + r * QSTR + c) * 2u,
                 Kg + (size_t)(t0 + r) * KVW + c);
        }
#pragma unroll
        for (int i = 0; i < 2; i++) {
            const int idx = tid + i * 256;
            const int r = idx >> 3, c = (idx & 7) * 8;
            cp16(smb + (uint32_t)(VOFFH + buf * KBUF + r * QSTR + c) * 2u,
                 Vg + (size_t)(t0 + r) * KVW + c);
        }
    };

#pragma unroll
    for (int i = 0; i < 4; i++) {
        const int idx = tid + i * 256;
        const int r = idx >> 3, c = (idx & 7) * 8;
        cp16(smb + (uint32_t)(r * QSTR + c) * 2u, Qg + (size_t)r * DM + c);
    }
    ldkv(0, 0);
    cp_commit();

    float lsA = 0.f, lsB = 0.f;
    float oacc[8][4];
#pragma unroll
    for (int n = 0; n < 8; n++)
#pragma unroll
        for (int j = 0; j < 4; j++) oacc[n][j] = 0.f;

    cp_wait<0>();
    __syncthreads();
    ldkv(1, 1);
    cp_commit();

    const uint32_t qoff = smb + (uint32_t)((wid * 16 + l15) * QSTR + kh) * 2u;
    uint32_t qf[4][4];
#pragma unroll
    for (int ks = 0; ks < 4; ks++)
        ldsm4(qf[ks][0], qf[ks][1], qf[ks][2], qf[ks][3], qoff + (uint32_t)(ks * 32));

    const uint32_t loff = (uint32_t)(l15 * QSTR + kh) * 2u;
    const uint32_t vtoff =
        (uint32_t)((((lane & 7) + ((lane >> 3) & 1) * 8) * QSTR) + (lane >> 4) * 8) * 2u;

    for (int ch = 0; ch < 8; ch++) {
        if (ch > 0) {
            cp_wait<0>();
            __syncthreads();
            if (ch < 7) { ldkv(ch + 1, (ch + 1) & 1); cp_commit(); }
        }
        const uint32_t kb_base = smb + (uint32_t)(KOFFH + (ch & 1) * KBUF) * 2u + loff;
        const uint32_t vb_base = smb + (uint32_t)(VOFFH + (ch & 1) * KBUF) * 2u + vtoff;

        float sacc[8][4];
#pragma unroll
        for (int n = 0; n < 8; n++)
#pragma unroll
            for (int j = 0; j < 4; j++) sacc[n][j] = 0.f;

#pragma unroll
        for (int ks = 0; ks < 4; ks++) {
#pragma unroll
            for (int nb = 0; nb < 4; nb++) {
                uint32_t q0, q1, q2, q3;
                ldsm4(q0, q1, q2, q3,
                      kb_base + (uint32_t)(nb * 16 * QSTR * 2 + ks * 32));
                uint32_t bf0[2] = {q0, q2}, bf1[2] = {q1, q3};
                mma_f16(sacc[2 * nb],     qf[ks], bf0);
                mma_f16(sacc[2 * nb + 1], qf[ks], bf1);
            }
        }

        uint32_t ph[8][2];
#pragma unroll
        for (int n = 0; n < 8; n++) {
            float e0 = exp2f(sacc[n][0]);
            float e1 = exp2f(sacc[n][1]);
            float e2 = exp2f(sacc[n][2]);
            float e3 = exp2f(sacc[n][3]);
            lsA += e0 + e1;
            lsB += e2 + e3;
            ph[n][0] = h2pack(e0, e1);
            ph[n][1] = h2pack(e2, e3);
        }

#pragma unroll
        for (int kbv = 0; kbv < 4; kbv++) {
            uint32_t a[4];
            a[0] = ph[2 * kbv][0];
            a[1] = ph[2 * kbv][1];
            a[2] = ph[2 * kbv + 1][0];
            a[3] = ph[2 * kbv + 1][1];
#pragma unroll
            for (int nd = 0; nd < 4; nd++) {
                uint32_t r0, r1, r2, r3;
                ldsm4t(r0, r1, r2, r3,
                       vb_base + (uint32_t)(kbv * 16 * QSTR * 2 + nd * 32));
                uint32_t bf0[2] = {r0, r1}, bf1[2] = {r2, r3};
                mma_f16(oacc[2 * nd],     a, bf0);
                mma_f16(oacc[2 * nd + 1], a, bf1);
            }
        }
    }

    lsA += __shfl_xor_sync(0xffffffffu, lsA, 1);
    lsA += __shfl_xor_sync(0xffffffffu, lsA, 2);
    lsB += __shfl_xor_sync(0xffffffffu, lsB, 1);
    lsB += __shfl_xor_sync(0xffffffffu, lsB, 2);
    const float invA = 1.f / lsA;
    const float invB = 1.f / lsB;
    __half* Og = g_o + ((size_t)b * SS + sblk * 128 + wid * 16 + g) * DM + h * HD;
#pragma unroll
    for (int nd = 0; nd < 8; nd++) {
        const int cc = nd * 8 + 2 * qd;
        *(uint32_t*)(Og + cc) = h2pack(oacc[nd][0] * invA, oacc[nd][1] * invA);
        *(uint32_t*)(Og + (size_t)8 * DM + cc) = h2pack(oacc[nd][2] * invB, oacc[nd][3] * invB);
    }
}

// ---------------- fused preamble: conv_x + 3 transposes + layernorm ------------------
#define NCONV 16384
#define NTRQ  1024
#define NTRKV 192
#define NTRO  1024
__device__ __forceinline__ void do_transpose(const float* __restrict__ src,
                                             __half* __restrict__ dst,
                                             int R, int C, int bx, int by,
                                             float (*t)[33]) {
    const int c0 = bx * 32, r0 = by * 32;
    const int x = threadIdx.x & 31, y = threadIdx.x >> 5;
#pragma unroll
    for (int i = 0; i < 32; i += 8) t[y + i][x] = src[(size_t)(r0 + y + i) * C + c0 + x];
    __syncthreads();
#pragma unroll
    for (int i = 0; i < 32; i += 8)
        dst[(size_t)(c0 + y + i) * R + r0 + x] = __float2half_rn(t[x][y + i]);
}

__global__ void pre_k(const float* __restrict__ x,
                      const float* __restrict__ text,
                      const float* __restrict__ ln_w,
                      const float* __restrict__ ln_b,
                      const float* __restrict__ Wq,
                      const float* __restrict__ Wkv,
                      const float* __restrict__ Wout) {
    __shared__ float tb[32][33];
    const int id = blockIdx.x;
    if (id < NCONV) {
        const size_t i = (size_t)id * 256 + threadIdx.x;
        float4 v = ((const float4*)x)[i];
        uint2 o;
        o.x = h2pack(v.x, v.y);
        o.y = h2pack(v.z, v.w);
        ((uint2*)g_xh)[i] = o;
    } else if (id < NCONV + NTRQ) {
        const int j = id - NCONV;
        do_transpose(Wq, g_wqt, DM, DM, j & 31, j >> 5, tb);
    } else if (id < NCONV + NTRQ + NTRKV) {
        const int j = id - NCONV - NTRQ;
        do_transpose(Wkv, g_wkvt, DT, KVW, j & 7, j >> 3, tb);
    } else if (id < NCONV + NTRQ + NTRKV + NTRO) {
        const int j = id - NCONV - NTRQ - NTRKV;
        do_transpose(Wout, g_woutt, DM, DM, j & 31, j >> 5, tb);
    } else {
        const int row = id - NCONV - NTRQ - NTRKV - NTRO;
        const float* xr = text + (size_t)row * DT;
        __half* out = g_tn + (size_t)row * DT;
        float v[3];
        float s = 0.f, s2 = 0.f;
#pragma unroll
        for (int i = 0; i < 3; i++) {
            v[i] = xr[threadIdx.x + i * 256];
            s += v[i]; s2 += v[i] * v[i];
        }
#pragma unroll
        for (int o = 16; o > 0; o >>= 1) {
            s  += __shfl_xor_sync(0xffffffffu, s,  o);
            s2 += __shfl_xor_sync(0xffffffffu, s2, o);
        }
        float* rs = &tb[0][0];
        const int wid = threadIdx.x >> 5, lid = threadIdx.x & 31;
        if (lid == 0) { rs[wid] = s; rs[8 + wid] = s2; }
        __syncthreads();
        float ts = 0.f, ts2 = 0.f;
#pragma unroll
        for (int i = 0; i < 8; i++) { ts += rs[i]; ts2 += rs[8 + i]; }
        const float mu = ts / (float)DT;
        const float inv = rsqrtf(ts2 / (float)DT - mu * mu + 1e-5f);
#pragma unroll
        for (int i = 0; i < 3; i++) {
            const int c = threadIdx.x + i * 256;
            out[c] = __float2half_rn((v[i] - mu) * inv * ln_w[c] + ln_b[c]);
        }
    }
}

// ---------------- launch -----------------------------------------------------------------
extern "C" void kernel_launch(void* const* d_in, const int* in_sizes, int n_in,
                              void* d_out, int out_size) {
    const float* x    = (const float*)d_in[0];
    const float* text = (const float*)d_in[1];
    const float* ln_w = (const float*)d_in[2];
    const float* ln_b = (const float*)d_in[3];
    const float* Wq   = (const float*)d_in[4];
    const float* Wkv  = (const float*)d_in[5];
    const float* Wout = (const float*)d_in[6];
    const float* bout = (const float*)d_in[7];
    float* out = (float*)d_out;

    const int GEMMSM = 3 * STGB;                        // 110592 B
    const int FLSM   = (9216 + 4 * KBUF) * 2;           // 55296 B
    cudaFuncSetAttribute(qkv_gemm_k, cudaFuncAttributeMaxDynamicSharedMemorySize, GEMMSM);
    cudaFuncSetAttribute(out_gemm_k, cudaFuncAttributeMaxDynamicSharedMemorySize, GEMMSM);
    cudaFuncSetAttribute(flash_k,    cudaFuncAttributeMaxDynamicSharedMemorySize, FLSM);

    int nsm = 148;
    cudaDeviceGetAttribute(&nsm, cudaDevAttrMultiProcessorCount, 0);
    const int G = 2 * nsm;              // persistent grid: 2 CTAs per SM

    pre_k<<<NCONV + NTRQ + NTRKV + NTRO + BB * TT, 256>>>(x, text, ln_w, ln_b, Wq, Wkv, Wout);

    qkv_gemm_k<<<G, 256, GEMMSM>>>();

    flash_k<<<dim3(SS / 128, BB * NH), 256, FLSM>>>();

    out_gemm_k<<<G, 256, GEMMSM>>>(bout, out);
}

// round 12
// speedup vs baseline: 1.0697x; 1.0697x over previous
#include <cuda_runtime.h>
#include <cuda_fp16.h>
#include <cstdint>
#include <cstddef>
#include <math.h>

#define BB   4
#define SS   4096
#define TT   512
#define DM   1024
#define DT   768
#define NH   16
#define NKVH 2
#define HD   64
#define REPH 8
#define KVW  256

// ---------------- scratch (all half) ------------------------------------------
__device__ __half g_xh [(size_t)BB * SS * DM];
__device__ __half g_tn [(size_t)BB * TT * DT];
__device__ __half g_kv [(size_t)BB * TT * KVW];
__device__ __half g_q  [(size_t)BB * SS * DM];
__device__ __half g_o  [(size_t)BB * SS * DM];
__device__ __half g_wqt  [(size_t)DM * DM];
__device__ __half g_wkvt [(size_t)KVW * DT];
__device__ __half g_woutt[(size_t)DM * DM];

// ---------------- PTX helpers ---------------------------------------------------
__device__ __forceinline__ uint32_t smem_u32(const void* p) {
    uint32_t a;
    asm("{ .reg .u64 t; cvta.to.shared.u64 t, %1; cvt.u32.u64 %0, t; }" : "=r"(a) : "l"(p));
    return a;
}
__device__ __forceinline__ void cp16(uint32_t s, const void* g) {
    asm volatile("cp.async.cg.shared.global [%0], [%1], 16;" :: "r"(s), "l"(g));
}
__device__ __forceinline__ void cp_commit() { asm volatile("cp.async.commit_group;"); }
template<int N> __device__ __forceinline__ void cp_wait() {
    asm volatile("cp.async.wait_group %0;" :: "n"(N) : "memory");
}
__device__ __forceinline__ uint32_t h2pack(float lo, float hi) {
    uint32_t r;
    asm("cvt.rn.f16x2.f32 %0, %1, %2;" : "=r"(r) : "f"(hi), "f"(lo));
    return r;
}
__device__ __forceinline__ void mma_f16(float* c, const uint32_t* a, const uint32_t* b) {
    asm volatile(
        "mma.sync.aligned.m16n8k16.row.col.f32.f16.f16.f32 "
        "{%0,%1,%2,%3}, {%4,%5,%6,%7}, {%8,%9}, {%0,%1,%2,%3};"
        : "+f"(c[0]), "+f"(c[1]), "+f"(c[2]), "+f"(c[3])
        : "r"(a[0]), "r"(a[1]), "r"(a[2]), "r"(a[3]), "r"(b[0]), "r"(b[1]));
}
__device__ __forceinline__ void ldsm4(uint32_t& r0, uint32_t& r1, uint32_t& r2, uint32_t& r3,
                                      uint32_t a) {
    asm volatile("ldmatrix.sync.aligned.m8n8.x4.shared.b16 {%0,%1,%2,%3}, [%4];"
                 : "=r"(r0), "=r"(r1), "=r"(r2), "=r"(r3) : "r"(a));
}
__device__ __forceinline__ void ldsm4t(uint32_t& r0, uint32_t& r1, uint32_t& r2, uint32_t& r3,
                                       uint32_t a) {
    asm volatile("ldmatrix.sync.aligned.m8n8.x4.trans.shared.b16 {%0,%1,%2,%3}, [%4];"
                 : "=r"(r0), "=r"(r1), "=r"(r2), "=r"(r3) : "r"(a));
}

#define GSTR 72                         // smem row stride (halfs) for 64-k slabs
#define QSCALE 0.1803368801111204f     // 0.125 * log2(e)

// ---------------- 128x128 fp16 GEMM: 64-k slabs, 3 stages, 2 CTAs/SM ---------------
// One barrier per slab: iter i+1's leading barrier already orders buffer reuse
// (loads into buf (i+3)%3 == i%3 happen only after all warps finished iter i reads).
template<bool FOUT>
__device__ __forceinline__ void gemm_body(const __half* __restrict__ A, int lda,
                                          const __half* __restrict__ B, int ldb,
                                          void* __restrict__ Cv, int ldc,
                                          int K, float scale,
                                          const float* __restrict__ bias,
                                          int row0, int col0) {
    constexpr int STG = 256 * GSTR;
    extern __shared__ __half hsm[];
    const uint32_t smb = smem_u32(hsm);

    const int tid  = threadIdx.x;
    const int wid  = tid >> 5;
    const int lane = tid & 31;
    const int R0   = (wid >> 2) * 64;
    const int C0   = (wid & 3) * 32;
    const int g    = lane >> 2;
    const int qd   = lane & 3;
    const int l15  = lane & 15;
    const int kh   = (lane >> 4) << 3;

    const uint32_t aoff = (uint32_t)((R0 + l15) * GSTR + kh) * 2u;
    const uint32_t boff = (uint32_t)((128 + C0 + l15) * GSTR + kh) * 2u;

    float acc[4][4][4];
#pragma unroll
    for (int m = 0; m < 4; m++)
#pragma unroll
        for (int n = 0; n < 4; n++)
#pragma unroll
            for (int j = 0; j < 4; j++) acc[m][n][j] = 0.f;

    const int nslab = K >> 6;

    auto load_slab = [&](int slab, int buf) {
        const int k0 = slab * 64;
        const uint32_t base = smb + (uint32_t)(buf * STG) * 2u;
#pragma unroll
        for (int t = 0; t < 4; t++) {
            const int idx = tid + t * 256;
            const int r = idx >> 3, c = (idx & 7) * 8;
            cp16(base + (uint32_t)(r * GSTR + c) * 2u,
                 A + (size_t)(row0 + r) * lda + k0 + c);
        }
#pragma unroll
        for (int t = 0; t < 4; t++) {
            const int idx = tid + t * 256;
            const int r = idx >> 3, c = (idx & 7) * 8;
            cp16(base + (uint32_t)((128 + r) * GSTR + c) * 2u,
                 B + (size_t)(col0 + r) * ldb + k0 + c);
        }
    };

    const int npro = (nslab < 2) ? nslab : 2;
    for (int p = 0; p < npro; p++) { load_slab(p, p); cp_commit(); }

    for (int i = 0; i < nslab; i++) {
        if (i + 1 < nslab) cp_wait<1>(); else cp_wait<0>();
        __syncthreads();
        if (i + 2 < nslab) { load_slab(i + 2, (i + 2) % 3); cp_commit(); }

        const uint32_t sbase = smb + (uint32_t)((i % 3) * STG) * 2u;
#pragma unroll
        for (int ks = 0; ks < 4; ks++) {
            const uint32_t kb = (uint32_t)(ks * 32);
            uint32_t af[4][4], bf[4][2];
#pragma unroll
            for (int m = 0; m < 4; m++)
                ldsm4(af[m][0], af[m][1], af[m][2], af[m][3],
                      sbase + aoff + (uint32_t)(m * 16 * GSTR * 2) + kb);
#pragma unroll
            for (int nb = 0; nb < 2; nb++) {
                uint32_t q0, q1, q2, q3;
                ldsm4(q0, q1, q2, q3,
                      sbase + boff + (uint32_t)(nb * 16 * GSTR * 2) + kb);
                bf[2 * nb][0] = q0; bf[2 * nb][1] = q2;
                bf[2 * nb + 1][0] = q1; bf[2 * nb + 1][1] = q3;
            }
#pragma unroll
            for (int m = 0; m < 4; m++)
#pragma unroll
                for (int n = 0; n < 4; n++)
                    mma_f16(acc[m][n], af[m], bf[n]);
        }
    }

#pragma unroll
    for (int m = 0; m < 4; m++) {
#pragma unroll
        for (int n = 0; n < 4; n++) {
            const int cc = col0 + C0 + n * 8 + qd * 2;
            const int r0 = row0 + R0 + m * 16 + g;
            if (FOUT) {
                float b0 = __ldg(bias + cc), b1 = __ldg(bias + cc + 1);
                float* C = (float*)Cv;
                *(float2*)(C + (size_t)r0 * ldc + cc) =
                    make_float2(acc[m][n][0] * scale + b0, acc[m][n][1] * scale + b1);
                *(float2*)(C + (size_t)(r0 + 8) * ldc + cc) =
                    make_float2(acc[m][n][2] * scale + b0, acc[m][n][3] * scale + b1);
            } else {
                __half* C = (__half*)Cv;
                *(uint32_t*)(C + (size_t)r0 * ldc + cc) =
                    h2pack(acc[m][n][0] * scale, acc[m][n][1] * scale);
                *(uint32_t*)(C + (size_t)(r0 + 8) * ldc + cc) =
                    h2pack(acc[m][n][2] * scale, acc[m][n][3] * scale);
            }
        }
    }
}

// ---------------- fused Q + KV projections (one launch) -----------------------------
__global__ void __launch_bounds__(256, 2)
qkv_gemm_k() {
    const int id = blockIdx.x;
    if (id < 1024) {
        gemm_body<false>(g_xh, DM, g_wqt, DM, g_q, DM, DM, QSCALE, nullptr,
                         (id >> 3) * 128, (id & 7) * 128);
    } else {
        const int kid = id - 1024;
        gemm_body<false>(g_tn, DT, g_wkvt, DT, g_kv, KVW, DT, 1.f, nullptr,
                         (kid >> 1) * 128, (kid & 1) * 128);
    }
}
__global__ void __launch_bounds__(256, 2)
out_gemm_k(const float* __restrict__ bout, float* __restrict__ out) {
    gemm_body<true>(g_o, DM, g_woutt, DM, out, DM, DM, 1.f, bout,
                    blockIdx.y * 128, blockIdx.x * 128);
}

// ---------------- fused flash attention: Tc=64, V via ldmatrix.trans ----------------
// smem halfs: Q[128][72] | K0 K1 V0 V1 (each 64x72)
#define QSTR 72
#define KBUF 4608
#define KOFFH 9216
#define VOFFH (9216 + 2 * KBUF)
__global__ void __launch_bounds__(256, 2)
flash_k() {
    extern __shared__ __half hsm[];
    const int sblk = blockIdx.x;
    const int b = blockIdx.y / NH, h = blockIdx.y % NH, gg = h / REPH;
    const int tid = threadIdx.x, wid = tid >> 5, lane = tid & 31;
    const int g = lane >> 2, qd = lane & 3;
    const int l15 = lane & 15;
    const int kh  = (lane >> 4) << 3;
    const uint32_t smb = smem_u32(hsm);

    const __half* Qg = g_q + ((size_t)b * SS + sblk * 128) * DM + h * HD;
    const __half* Kg = g_kv + (size_t)b * TT * KVW + gg * HD;
    const __half* Vg = g_kv + (size_t)b * TT * KVW + NKVH * HD + gg * HD;

    auto ldkv = [&](int chunk, int buf) {
        const int t0 = chunk * 64;
#pragma unroll
        for (int i = 0; i < 2; i++) {
            const int idx = tid + i * 256;
            const int r = idx >> 3, c = (idx & 7) * 8;
            cp16(smb + (uint32_t)(KOFFH + buf * KBUF + r * QSTR + c) * 2u,
                 Kg + (size_t)(t0 + r) * KVW + c);
        }
#pragma unroll
        for (int i = 0; i < 2; i++) {
            const int idx = tid + i * 256;
            const int r = idx >> 3, c = (idx & 7) * 8;
            cp16(smb + (uint32_t)(VOFFH + buf * KBUF + r * QSTR + c) * 2u,
                 Vg + (size_t)(t0 + r) * KVW + c);
        }
    };

    // prologue: Q + chunk 0
#pragma unroll
    for (int i = 0; i < 4; i++) {
        const int idx = tid + i * 256;
        const int r = idx >> 3, c = (idx & 7) * 8;
        cp16(smb + (uint32_t)(r * QSTR + c) * 2u, Qg + (size_t)r * DM + c);
    }
    ldkv(0, 0);
    cp_commit();

    float lsA = 0.f, lsB = 0.f;
    float oacc[8][4];
#pragma unroll
    for (int n = 0; n < 8; n++)
#pragma unroll
        for (int j = 0; j < 4; j++) oacc[n][j] = 0.f;

    cp_wait<0>();
    __syncthreads();
    ldkv(1, 1);
    cp_commit();

    // Q fragments resident
    const uint32_t qoff = smb + (uint32_t)((wid * 16 + l15) * QSTR + kh) * 2u;
    uint32_t qf[4][4];
#pragma unroll
    for (int ks = 0; ks < 4; ks++)
        ldsm4(qf[ks][0], qf[ks][1], qf[ks][2], qf[ks][3], qoff + (uint32_t)(ks * 32));

    const uint32_t loff = (uint32_t)(l15 * QSTR + kh) * 2u;
    // trans-ldsm lane offset: k-row = (lane&7) + 8*((lane>>3)&1), n-base = (lane>>4)*8
    const uint32_t vtoff =
        (uint32_t)((((lane & 7) + ((lane >> 3) & 1) * 8) * QSTR) + (lane >> 4) * 8) * 2u;

    for (int ch = 0; ch < 8; ch++) {
        if (ch > 0) {
            cp_wait<0>();
            __syncthreads();
            if (ch < 7) { ldkv(ch + 1, (ch + 1) & 1); cp_commit(); }
        }
        const uint32_t kb_base = smb + (uint32_t)(KOFFH + (ch & 1) * KBUF) * 2u + loff;
        const uint32_t vb_base = smb + (uint32_t)(VOFFH + (ch & 1) * KBUF) * 2u + vtoff;

        // ---- S = Q K^T (128 x 64) ----
        float sacc[8][4];
#pragma unroll
        for (int n = 0; n < 8; n++)
#pragma unroll
            for (int j = 0; j < 4; j++) sacc[n][j] = 0.f;

#pragma unroll
        for (int ks = 0; ks < 4; ks++) {
#pragma unroll
            for (int nb = 0; nb < 4; nb++) {
                uint32_t q0, q1, q2, q3;
                ldsm4(q0, q1, q2, q3,
                      kb_base + (uint32_t)(nb * 16 * QSTR * 2 + ks * 32));
                uint32_t bf0[2] = {q0, q2}, bf1[2] = {q1, q3};
                mma_f16(sacc[2 * nb],     qf[ks], bf0);
                mma_f16(sacc[2 * nb + 1], qf[ks], bf1);
            }
        }

        // ---- softmax: plain exp2 (scores pre-scaled by log2e/8) ----
        uint32_t ph[8][2];
#pragma unroll
        for (int n = 0; n < 8; n++) {
            float e0 = exp2f(sacc[n][0]);
            float e1 = exp2f(sacc[n][1]);
            float e2 = exp2f(sacc[n][2]);
            float e3 = exp2f(sacc[n][3]);
            lsA += e0 + e1;
            lsB += e2 + e3;
            ph[n][0] = h2pack(e0, e1);
            ph[n][1] = h2pack(e2, e3);
        }

        // ---- O += P V ----
#pragma unroll
        for (int kbv = 0; kbv < 4; kbv++) {
            uint32_t a[4];
            a[0] = ph[2 * kbv][0];
            a[1] = ph[2 * kbv][1];
            a[2] = ph[2 * kbv + 1][0];
            a[3] = ph[2 * kbv + 1][1];
#pragma unroll
            for (int nd = 0; nd < 4; nd++) {
                uint32_t r0, r1, r2, r3;
                ldsm4t(r0, r1, r2, r3,
                       vb_base + (uint32_t)(kbv * 16 * QSTR * 2 + nd * 32));
                uint32_t bf0[2] = {r0, r1}, bf1[2] = {r2, r3};
                mma_f16(oacc[2 * nd],     a, bf0);
                mma_f16(oacc[2 * nd + 1], a, bf1);
            }
        }
    }

    lsA += __shfl_xor_sync(0xffffffffu, lsA, 1);
    lsA += __shfl_xor_sync(0xffffffffu, lsA, 2);
    lsB += __shfl_xor_sync(0xffffffffu, lsB, 1);
    lsB += __shfl_xor_sync(0xffffffffu, lsB, 2);
    const float invA = 1.f / lsA;
    const float invB = 1.f / lsB;
    __half* Og = g_o + ((size_t)b * SS + sblk * 128 + wid * 16 + g) * DM + h * HD;
#pragma unroll
    for (int nd = 0; nd < 8; nd++) {
        const int cc = nd * 8 + 2 * qd;
        *(uint32_t*)(Og + cc) = h2pack(oacc[nd][0] * invA, oacc[nd][1] * invA);
        *(uint32_t*)(Og + (size_t)8 * DM + cc) = h2pack(oacc[nd][2] * invB, oacc[nd][3] * invB);
    }
}

// ---------------- fused preamble: conv_x + 3 transposes + layernorm ------------------
#define NCONV 16384
#define NTRQ  1024
#define NTRKV 192
#define NTRO  1024
__device__ __forceinline__ void do_transpose(const float* __restrict__ src,
                                             __half* __restrict__ dst,
                                             int R, int C, int bx, int by,
                                             float (*t)[33]) {
    const int c0 = bx * 32, r0 = by * 32;
    const int x = threadIdx.x & 31, y = threadIdx.x >> 5;
#pragma unroll
    for (int i = 0; i < 32; i += 8) t[y + i][x] = src[(size_t)(r0 + y + i) * C + c0 + x];
    __syncthreads();
#pragma unroll
    for (int i = 0; i < 32; i += 8)
        dst[(size_t)(c0 + y + i) * R + r0 + x] = __float2half_rn(t[x][y + i]);
}

__global__ void pre_k(const float* __restrict__ x,
                      const float* __restrict__ text,
                      const float* __restrict__ ln_w,
                      const float* __restrict__ ln_b,
                      const float* __restrict__ Wq,
                      const float* __restrict__ Wkv,
                      const float* __restrict__ Wout) {
    __shared__ float tb[32][33];
    const int id = blockIdx.x;
    if (id < NCONV) {
        const size_t i = (size_t)id * 256 + threadIdx.x;
        float4 v = ((const float4*)x)[i];
        uint2 o;
        o.x = h2pack(v.x, v.y);
        o.y = h2pack(v.z, v.w);
        ((uint2*)g_xh)[i] = o;
    } else if (id < NCONV + NTRQ) {
        const int j = id - NCONV;
        do_transpose(Wq, g_wqt, DM, DM, j & 31, j >> 5, tb);
    } else if (id < NCONV + NTRQ + NTRKV) {
        const int j = id - NCONV - NTRQ;
        do_transpose(Wkv, g_wkvt, DT, KVW, j & 7, j >> 3, tb);
    } else if (id < NCONV + NTRQ + NTRKV + NTRO) {
        const int j = id - NCONV - NTRQ - NTRKV;
        do_transpose(Wout, g_woutt, DM, DM, j & 31, j >> 5, tb);
    } else {
        const int row = id - NCONV - NTRQ - NTRKV - NTRO;
        const float* xr = text + (size_t)row * DT;
        __half* out = g_tn + (size_t)row * DT;
        float v[3];
        float s = 0.f, s2 = 0.f;
#pragma unroll
        for (int i = 0; i < 3; i++) {
            v[i] = xr[threadIdx.x + i * 256];
            s += v[i]; s2 += v[i] * v[i];
        }
#pragma unroll
        for (int o = 16; o > 0; o >>= 1) {
            s  += __shfl_xor_sync(0xffffffffu, s,  o);
            s2 += __shfl_xor_sync(0xffffffffu, s2, o);
        }
        float* rs = &tb[0][0];
        const int wid = threadIdx.x >> 5, lid = threadIdx.x & 31;
        if (lid == 0) { rs[wid] = s; rs[8 + wid] = s2; }
        __syncthreads();
        float ts = 0.f, ts2 = 0.f;
#pragma unroll
        for (int i = 0; i < 8; i++) { ts += rs[i]; ts2 += rs[8 + i]; }
        const float mu = ts / (float)DT;
        const float inv = rsqrtf(ts2 / (float)DT - mu * mu + 1e-5f);
#pragma unroll
        for (int i = 0; i < 3; i++) {
            const int c = threadIdx.x + i * 256;
            out[c] = __float2half_rn((v[i] - mu) * inv * ln_w[c] + ln_b[c]);
        }
    }
}

// ---------------- launch -----------------------------------------------------------------
extern "C" void kernel_launch(void* const* d_in, const int* in_sizes, int n_in,
                              void* d_out, int out_size) {
    const float* x    = (const float*)d_in[0];
    const float* text = (const float*)d_in[1];
    const float* ln_w = (const float*)d_in[2];
    const float* ln_b = (const float*)d_in[3];
    const float* Wq   = (const float*)d_in[4];
    const float* Wkv  = (const float*)d_in[5];
    const float* Wout = (const float*)d_in[6];
    const float* bout = (const float*)d_in[7];
    float* out = (float*)d_out;

    const int GEMMSM = 3 * 256 * GSTR * 2;              // 110592 B
    const int FLSM   = (9216 + 4 * KBUF) * 2;           // 55296 B
    cudaFuncSetAttribute(qkv_gemm_k, cudaFuncAttributeMaxDynamicSharedMemorySize, GEMMSM);
    cudaFuncSetAttribute(out_gemm_k, cudaFuncAttributeMaxDynamicSharedMemorySize, GEMMSM);
    cudaFuncSetAttribute(flash_k,    cudaFuncAttributeMaxDynamicSharedMemorySize, FLSM);

    pre_k<<<NCONV + NTRQ + NTRKV + NTRO + BB * TT, 256>>>(x, text, ln_w, ln_b, Wq, Wkv, Wout);

    qkv_gemm_k<<<1024 + 32, 256, GEMMSM>>>();

    flash_k<<<dim3(SS / 128, BB * NH), 256, FLSM>>>();

    out_gemm_k<<<dim3(DM / 128, (BB * SS) / 128), 256, GEMMSM>>>(bout, out);
}

// round 13
// speedup vs baseline: 1.0715x; 1.0016x over previous
#include <cuda_runtime.h>
#include <cuda_fp16.h>
#include <cstdint>
#include <cstddef>
#include <math.h>

#define BB   4
#define SS   4096
#define TT   512
#define DM   1024
#define DT   768
#define NH   16
#define NKVH 2
#define HD   64
#define REPH 8
#define KVW  256

// ---------------- scratch (all half) ------------------------------------------
__device__ __half g_xh [(size_t)BB * SS * DM];
__device__ __half g_tn [(size_t)BB * TT * DT];
__device__ __half g_kv [(size_t)BB * TT * KVW];
__device__ __half g_q  [(size_t)BB * SS * DM];
__device__ __half g_o  [(size_t)BB * SS * DM];
__device__ __half g_wqt  [(size_t)DM * DM];
__device__ __half g_wkvt [(size_t)KVW * DT];
__device__ __half g_woutt[(size_t)DM * DM];

// ---------------- PTX helpers ---------------------------------------------------
__device__ __forceinline__ uint32_t smem_u32(const void* p) {
    uint32_t a;
    asm("{ .reg .u64 t; cvta.to.shared.u64 t, %1; cvt.u32.u64 %0, t; }" : "=r"(a) : "l"(p));
    return a;
}
__device__ __forceinline__ void cp16(uint32_t s, const void* g) {
    asm volatile("cp.async.cg.shared.global [%0], [%1], 16;" :: "r"(s), "l"(g));
}
__device__ __forceinline__ void cp_commit() { asm volatile("cp.async.commit_group;"); }
template<int N> __device__ __forceinline__ void cp_wait() {
    asm volatile("cp.async.wait_group %0;" :: "n"(N) : "memory");
}
__device__ __forceinline__ uint32_t h2pack(float lo, float hi) {
    uint32_t r;
    asm("cvt.rn.f16x2.f32 %0, %1, %2;" : "=r"(r) : "f"(hi), "f"(lo));
    return r;
}
__device__ __forceinline__ void mma_f16(float* c, const uint32_t* a, const uint32_t* b) {
    asm volatile(
        "mma.sync.aligned.m16n8k16.row.col.f32.f16.f16.f32 "
        "{%0,%1,%2,%3}, {%4,%5,%6,%7}, {%8,%9}, {%0,%1,%2,%3};"
        : "+f"(c[0]), "+f"(c[1]), "+f"(c[2]), "+f"(c[3])
        : "r"(a[0]), "r"(a[1]), "r"(a[2]), "r"(a[3]), "r"(b[0]), "r"(b[1]));
}
__device__ __forceinline__ void ldsm4(uint32_t& r0, uint32_t& r1, uint32_t& r2, uint32_t& r3,
                                      uint32_t a) {
    asm volatile("ldmatrix.sync.aligned.m8n8.x4.shared.b16 {%0,%1,%2,%3}, [%4];"
                 : "=r"(r0), "=r"(r1), "=r"(r2), "=r"(r3) : "r"(a));
}
__device__ __forceinline__ void ldsm4t(uint32_t& r0, uint32_t& r1, uint32_t& r2, uint32_t& r3,
                                       uint32_t a) {
    asm volatile("ldmatrix.sync.aligned.m8n8.x4.trans.shared.b16 {%0,%1,%2,%3}, [%4];"
                 : "=r"(r0), "=r"(r1), "=r"(r2), "=r"(r3) : "r"(a));
}

#define GSTR 72                         // smem row stride (halfs) for 64-k slabs
#define QSCALE 0.1803368801111204f     // 0.125 * log2(e)

// ---------------- 128x128 fp16 GEMM: 64-k slabs, 3 stages, 2 CTAs/SM ---------------
template<bool FOUT>
__device__ __forceinline__ void gemm_body(const __half* __restrict__ A, int lda,
                                          const __half* __restrict__ B, int ldb,
                                          void* __restrict__ Cv, int ldc,
                                          int K, float scale,
                                          const float* __restrict__ bias,
                                          int row0, int col0) {
    constexpr int STG = 256 * GSTR;
    extern __shared__ __half hsm[];
    const uint32_t smb = smem_u32(hsm);

    const int tid  = threadIdx.x;
    const int wid  = tid >> 5;
    const int lane = tid & 31;
    const int R0   = (wid >> 2) * 64;
    const int C0   = (wid & 3) * 32;
    const int g    = lane >> 2;
    const int qd   = lane & 3;
    const int l15  = lane & 15;
    const int kh   = (lane >> 4) << 3;

    const uint32_t aoff = (uint32_t)((R0 + l15) * GSTR + kh) * 2u;
    const uint32_t boff = (uint32_t)((128 + C0 + l15) * GSTR + kh) * 2u;

    float acc[4][4][4];
#pragma unroll
    for (int m = 0; m < 4; m++)
#pragma unroll
        for (int n = 0; n < 4; n++)
#pragma unroll
            for (int j = 0; j < 4; j++) acc[m][n][j] = 0.f;

    const int nslab = K >> 6;

    auto load_slab = [&](int slab, int buf) {
        const int k0 = slab * 64;
        const uint32_t base = smb + (uint32_t)(buf * STG) * 2u;
#pragma unroll
        for (int t = 0; t < 4; t++) {
            const int idx = tid + t * 256;
            const int r = idx >> 3, c = (idx & 7) * 8;
            cp16(base + (uint32_t)(r * GSTR + c) * 2u,
                 A + (size_t)(row0 + r) * lda + k0 + c);
        }
#pragma unroll
        for (int t = 0; t < 4; t++) {
            const int idx = tid + t * 256;
            const int r = idx >> 3, c = (idx & 7) * 8;
            cp16(base + (uint32_t)((128 + r) * GSTR + c) * 2u,
                 B + (size_t)(col0 + r) * ldb + k0 + c);
        }
    };

    const int npro = (nslab < 2) ? nslab : 2;
    for (int p = 0; p < npro; p++) { load_slab(p, p); cp_commit(); }

    for (int i = 0; i < nslab; i++) {
        if (i + 1 < nslab) cp_wait<1>(); else cp_wait<0>();
        __syncthreads();
        if (i + 2 < nslab) { load_slab(i + 2, (i + 2) % 3); cp_commit(); }

        const uint32_t sbase = smb + (uint32_t)((i % 3) * STG) * 2u;
#pragma unroll
        for (int ks = 0; ks < 4; ks++) {
            const uint32_t kb = (uint32_t)(ks * 32);
            uint32_t af[4][4], bf[4][2];
#pragma unroll
            for (int m = 0; m < 4; m++)
                ldsm4(af[m][0], af[m][1], af[m][2], af[m][3],
                      sbase + aoff + (uint32_t)(m * 16 * GSTR * 2) + kb);
#pragma unroll
            for (int nb = 0; nb < 2; nb++) {
                uint32_t q0, q1, q2, q3;
                ldsm4(q0, q1, q2, q3,
                      sbase + boff + (uint32_t)(nb * 16 * GSTR * 2) + kb);
                bf[2 * nb][0] = q0; bf[2 * nb][1] = q2;
                bf[2 * nb + 1][0] = q1; bf[2 * nb + 1][1] = q3;
            }
#pragma unroll
            for (int m = 0; m < 4; m++)
#pragma unroll
                for (int n = 0; n < 4; n++)
                    mma_f16(acc[m][n], af[m], bf[n]);
        }
    }

#pragma unroll
    for (int m = 0; m < 4; m++) {
#pragma unroll
        for (int n = 0; n < 4; n++) {
            const int cc = col0 + C0 + n * 8 + qd * 2;
            const int r0 = row0 + R0 + m * 16 + g;
            if (FOUT) {
                float b0 = __ldg(bias + cc), b1 = __ldg(bias + cc + 1);
                float* C = (float*)Cv;
                *(float2*)(C + (size_t)r0 * ldc + cc) =
                    make_float2(acc[m][n][0] * scale + b0, acc[m][n][1] * scale + b1);
                *(float2*)(C + (size_t)(r0 + 8) * ldc + cc) =
                    make_float2(acc[m][n][2] * scale + b0, acc[m][n][3] * scale + b1);
            } else {
                __half* C = (__half*)Cv;
                *(uint32_t*)(C + (size_t)r0 * ldc + cc) =
                    h2pack(acc[m][n][0] * scale, acc[m][n][1] * scale);
                *(uint32_t*)(C + (size_t)(r0 + 8) * ldc + cc) =
                    h2pack(acc[m][n][2] * scale, acc[m][n][3] * scale);
            }
        }
    }
}

// ---------------- fused Q + KV projections (one launch, PDL consumer+producer) ------
__global__ void __launch_bounds__(256, 2)
qkv_gemm_k() {
#if __CUDA_ARCH__ >= 900
    cudaGridDependencySynchronize();
#endif
    const int id = blockIdx.x;
    if (id < 1024) {
        gemm_body<false>(g_xh, DM, g_wqt, DM, g_q, DM, DM, QSCALE, nullptr,
                         (id >> 3) * 128, (id & 7) * 128);
    } else {
        const int kid = id - 1024;
        gemm_body<false>(g_tn, DT, g_wkvt, DT, g_kv, KVW, DT, 1.f, nullptr,
                         (kid >> 1) * 128, (kid & 1) * 128);
    }
#if __CUDA_ARCH__ >= 900
    cudaTriggerProgrammaticLaunchCompletion();
#endif
}
__global__ void __launch_bounds__(256, 2)
out_gemm_k(const float* __restrict__ bout, float* __restrict__ out) {
#if __CUDA_ARCH__ >= 900
    cudaGridDependencySynchronize();
#endif
    gemm_body<true>(g_o, DM, g_woutt, DM, out, DM, DM, 1.f, bout,
                    blockIdx.y * 128, blockIdx.x * 128);
}

// ---------------- fused flash attention: Tc=64, V via ldmatrix.trans ----------------
// smem halfs: Q[128][72] | K0 K1 V0 V1 (each 64x72)
#define QSTR 72
#define KBUF 4608
#define KOFFH 9216
#define VOFFH (9216 + 2 * KBUF)
__global__ void __launch_bounds__(256, 2)
flash_k() {
#if __CUDA_ARCH__ >= 900
    cudaGridDependencySynchronize();
#endif
    extern __shared__ __half hsm[];
    const int sblk = blockIdx.x;
    const int b = blockIdx.y / NH, h = blockIdx.y % NH, gg = h / REPH;
    const int tid = threadIdx.x, wid = tid >> 5, lane = tid & 31;
    const int g = lane >> 2, qd = lane & 3;
    const int l15 = lane & 15;
    const int kh  = (lane >> 4) << 3;
    const uint32_t smb = smem_u32(hsm);

    const __half* Qg = g_q + ((size_t)b * SS + sblk * 128) * DM + h * HD;
    const __half* Kg = g_kv + (size_t)b * TT * KVW + gg * HD;
    const __half* Vg = g_kv + (size_t)b * TT * KVW + NKVH * HD + gg * HD;

    auto ldkv = [&](int chunk, int buf) {
        const int t0 = chunk * 64;
#pragma unroll
        for (int i = 0; i < 2; i++) {
            const int idx = tid + i * 256;
            const int r = idx >> 3, c = (idx & 7) * 8;
            cp16(smb + (uint32_t)(KOFFH + buf * KBUF + r * QSTR + c) * 2u,
                 Kg + (size_t)(t0 + r) * KVW + c);
        }
#pragma unroll
        for (int i = 0; i < 2; i++) {
            const int idx = tid + i * 256;
            const int r = idx >> 3, c = (idx & 7) * 8;
            cp16(smb + (uint32_t)(VOFFH + buf * KBUF + r * QSTR + c) * 2u,
                 Vg + (size_t)(t0 + r) * KVW + c);
        }
    };

    // prologue: Q + chunk 0
#pragma unroll
    for (int i = 0; i < 4; i++) {
        const int idx = tid + i * 256;
        const int r = idx >> 3, c = (idx & 7) * 8;
        cp16(smb + (uint32_t)(r * QSTR + c) * 2u, Qg + (size_t)r * DM + c);
    }
    ldkv(0, 0);
    cp_commit();

    float lsA = 0.f, lsB = 0.f;
    float oacc[8][4];
#pragma unroll
    for (int n = 0; n < 8; n++)
#pragma unroll
        for (int j = 0; j < 4; j++) oacc[n][j] = 0.f;

    cp_wait<0>();
    __syncthreads();
    ldkv(1, 1);
    cp_commit();

    // Q fragments resident
    const uint32_t qoff = smb + (uint32_t)((wid * 16 + l15) * QSTR + kh) * 2u;
    uint32_t qf[4][4];
#pragma unroll
    for (int ks = 0; ks < 4; ks++)
        ldsm4(qf[ks][0], qf[ks][1], qf[ks][2], qf[ks][3], qoff + (uint32_t)(ks * 32));

    const uint32_t loff = (uint32_t)(l15 * QSTR + kh) * 2u;
    const uint32_t vtoff =
        (uint32_t)((((lane & 7) + ((lane >> 3) & 1) * 8) * QSTR) + (lane >> 4) * 8) * 2u;

    for (int ch = 0; ch < 8; ch++) {
        if (ch > 0) {
            cp_wait<0>();
            __syncthreads();
            if (ch < 7) { ldkv(ch + 1, (ch + 1) & 1); cp_commit(); }
        }
        const uint32_t kb_base = smb + (uint32_t)(KOFFH + (ch & 1) * KBUF) * 2u + loff;
        const uint32_t vb_base = smb + (uint32_t)(VOFFH + (ch & 1) * KBUF) * 2u + vtoff;

        // ---- S = Q K^T (128 x 64) ----
        float sacc[8][4];
#pragma unroll
        for (int n = 0; n < 8; n++)
#pragma unroll
            for (int j = 0; j < 4; j++) sacc[n][j] = 0.f;

#pragma unroll
        for (int ks = 0; ks < 4; ks++) {
#pragma unroll
            for (int nb = 0; nb < 4; nb++) {
                uint32_t q0, q1, q2, q3;
                ldsm4(q0, q1, q2, q3,
                      kb_base + (uint32_t)(nb * 16 * QSTR * 2 + ks * 32));
                uint32_t bf0[2] = {q0, q2}, bf1[2] = {q1, q3};
                mma_f16(sacc[2 * nb],     qf[ks], bf0);
                mma_f16(sacc[2 * nb + 1], qf[ks], bf1);
            }
        }

        // ---- softmax: plain exp2 (scores pre-scaled by log2e/8) ----
        uint32_t ph[8][2];
#pragma unroll
        for (int n = 0; n < 8; n++) {
            float e0 = exp2f(sacc[n][0]);
            float e1 = exp2f(sacc[n][1]);
            float e2 = exp2f(sacc[n][2]);
            float e3 = exp2f(sacc[n][3]);
            lsA += e0 + e1;
            lsB += e2 + e3;
            ph[n][0] = h2pack(e0, e1);
            ph[n][1] = h2pack(e2, e3);
        }

        // ---- O += P V ----
#pragma unroll
        for (int kbv = 0; kbv < 4; kbv++) {
            uint32_t a[4];
            a[0] = ph[2 * kbv][0];
            a[1] = ph[2 * kbv][1];
            a[2] = ph[2 * kbv + 1][0];
            a[3] = ph[2 * kbv + 1][1];
#pragma unroll
            for (int nd = 0; nd < 4; nd++) {
                uint32_t r0, r1, r2, r3;
                ldsm4t(r0, r1, r2, r3,
                       vb_base + (uint32_t)(kbv * 16 * QSTR * 2 + nd * 32));
                uint32_t bf0[2] = {r0, r1}, bf1[2] = {r2, r3};
                mma_f16(oacc[2 * nd],     a, bf0);
                mma_f16(oacc[2 * nd + 1], a, bf1);
            }
        }
    }

    lsA += __shfl_xor_sync(0xffffffffu, lsA, 1);
    lsA += __shfl_xor_sync(0xffffffffu, lsA, 2);
    lsB += __shfl_xor_sync(0xffffffffu, lsB, 1);
    lsB += __shfl_xor_sync(0xffffffffu, lsB, 2);
    const float invA = 1.f / lsA;
    const float invB = 1.f / lsB;
    __half* Og = g_o + ((size_t)b * SS + sblk * 128 + wid * 16 + g) * DM + h * HD;
#pragma unroll
    for (int nd = 0; nd < 8; nd++) {
        const int cc = nd * 8 + 2 * qd;
        *(uint32_t*)(Og + cc) = h2pack(oacc[nd][0] * invA, oacc[nd][1] * invA);
        *(uint32_t*)(Og + (size_t)8 * DM + cc) = h2pack(oacc[nd][2] * invB, oacc[nd][3] * invB);
    }
#if __CUDA_ARCH__ >= 900
    cudaTriggerProgrammaticLaunchCompletion();
#endif
}

// ---------------- fused preamble: conv_x + 3 transposes + layernorm ------------------
#define NCONV 16384
#define NTRQ  1024
#define NTRKV 192
#define NTRO  1024
__device__ __forceinline__ void do_transpose(const float* __restrict__ src,
                                             __half* __restrict__ dst,
                                             int R, int C, int bx, int by,
                                             float (*t)[33]) {
    const int c0 = bx * 32, r0 = by * 32;
    const int x = threadIdx.x & 31, y = threadIdx.x >> 5;
#pragma unroll
    for (int i = 0; i < 32; i += 8) t[y + i][x] = src[(size_t)(r0 + y + i) * C + c0 + x];
    __syncthreads();
#pragma unroll
    for (int i = 0; i < 32; i += 8)
        dst[(size_t)(c0 + y + i) * R + r0 + x] = __float2half_rn(t[x][y + i]);
}

__global__ void pre_k(const float* __restrict__ x,
                      const float* __restrict__ text,
                      const float* __restrict__ ln_w,
                      const float* __restrict__ ln_b,
                      const float* __restrict__ Wq,
                      const float* __restrict__ Wkv,
                      const float* __restrict__ Wout) {
    __shared__ float tb[32][33];
    const int id = blockIdx.x;
    if (id < NCONV) {
        const size_t i = (size_t)id * 256 + threadIdx.x;
        float4 v = ((const float4*)x)[i];
        uint2 o;
        o.x = h2pack(v.x, v.y);
        o.y = h2pack(v.z, v.w);
        ((uint2*)g_xh)[i] = o;
    } else if (id < NCONV + NTRQ) {
        const int j = id - NCONV;
        do_transpose(Wq, g_wqt, DM, DM, j & 31, j >> 5, tb);
    } else if (id < NCONV + NTRQ + NTRKV) {
        const int j = id - NCONV - NTRQ;
        do_transpose(Wkv, g_wkvt, DT, KVW, j & 7, j >> 3, tb);
    } else if (id < NCONV + NTRQ + NTRKV + NTRO) {
        const int j = id - NCONV - NTRQ - NTRKV;
        do_transpose(Wout, g_woutt, DM, DM, j & 31, j >> 5, tb);
    } else {
        const int row = id - NCONV - NTRQ - NTRKV - NTRO;
        const float* xr = text + (size_t)row * DT;
        __half* out = g_tn + (size_t)row * DT;
        float v[3];
        float s = 0.f, s2 = 0.f;
#pragma unroll
        for (int i = 0; i < 3; i++) {
            v[i] = xr[threadIdx.x + i * 256];
            s += v[i]; s2 += v[i] * v[i];
        }
#pragma unroll
        for (int o = 16; o > 0; o >>= 1) {
            s  += __shfl_xor_sync(0xffffffffu, s,  o);
            s2 += __shfl_xor_sync(0xffffffffu, s2, o);
        }
        float* rs = &tb[0][0];
        const int wid = threadIdx.x >> 5, lid = threadIdx.x & 31;
        if (lid == 0) { rs[wid] = s; rs[8 + wid] = s2; }
        __syncthreads();
        float ts = 0.f, ts2 = 0.f;
#pragma unroll
        for (int i = 0; i < 8; i++) { ts += rs[i]; ts2 += rs[8 + i]; }
        const float mu = ts / (float)DT;
        const float inv = rsqrtf(ts2 / (float)DT - mu * mu + 1e-5f);
#pragma unroll
        for (int i = 0; i < 3; i++) {
            const int c = threadIdx.x + i * 256;
            out[c] = __float2half_rn((v[i] - mu) * inv * ln_w[c] + ln_b[c]);
        }
    }
#if __CUDA_ARCH__ >= 900
    cudaTriggerProgrammaticLaunchCompletion();
#endif
}

// ---------------- launch -----------------------------------------------------------------
static void launch_pdl(const void* fn, dim3 grid, dim3 block, int smem,
                       void** args) {
    cudaLaunchConfig_t cfg = {};
    cfg.gridDim = grid;
    cfg.blockDim = block;
    cfg.dynamicSmemBytes = (size_t)smem;
    cfg.stream = 0;
    cudaLaunchAttribute attr[1];
    attr[0].id = cudaLaunchAttributeProgrammaticStreamSerialization;
    attr[0].val.programmaticStreamSerializationAllowed = 1;
    cfg.attrs = attr;
    cfg.numAttrs = 1;
    cudaLaunchKernelExC(&cfg, fn, args);
}

extern "C" void kernel_launch(void* const* d_in, const int* in_sizes, int n_in,
                              void* d_out, int out_size) {
    const float* x    = (const float*)d_in[0];
    const float* text = (const float*)d_in[1];
    const float* ln_w = (const float*)d_in[2];
    const float* ln_b = (const float*)d_in[3];
    const float* Wq   = (const float*)d_in[4];
    const float* Wkv  = (const float*)d_in[5];
    const float* Wout = (const float*)d_in[6];
    const float* bout = (const float*)d_in[7];
    float* out = (float*)d_out;

    const int GEMMSM = 3 * 256 * GSTR * 2;              // 110592 B
    const int FLSM   = (9216 + 4 * KBUF) * 2;           // 55296 B
    cudaFuncSetAttribute(qkv_gemm_k, cudaFuncAttributeMaxDynamicSharedMemorySize, GEMMSM);
    cudaFuncSetAttribute(out_gemm_k, cudaFuncAttributeMaxDynamicSharedMemorySize, GEMMSM);
    cudaFuncSetAttribute(flash_k,    cudaFuncAttributeMaxDynamicSharedMemorySize, FLSM);

    pre_k<<<NCONV + NTRQ + NTRKV + NTRO + BB * TT, 256>>>(x, text, ln_w, ln_b, Wq, Wkv, Wout);

    {   // qkv: PDL consumer of pre_k
        void* args[] = {};
        launch_pdl((const void*)qkv_gemm_k, dim3(1024 + 32), dim3(256), GEMMSM, args);
    }
    {   // flash: PDL consumer of qkv
        void* args[] = {};
        launch_pdl((const void*)flash_k, dim3(SS / 128, BB * NH), dim3(256), FLSM, args);
    }
    {   // out: PDL consumer of flash
        void* args[] = {(void*)&bout, (void*)&out};
        launch_pdl((const void*)out_gemm_k, dim3(DM / 128, (BB * SS) / 128), dim3(256),
                   GEMMSM, args);
    }
}